// round 3
// baseline (speedup 1.0000x reference)
#include <cuda_runtime.h>
#include <cuda_bf16.h>
#include <stdint.h>

#define TPB   512
#define NNODE 49
#define PADN  64
#define BT    2
#define MROWS 128
#define DIM   768
#define C1    256
#define C2    128
#define NCLS  13
#define KT    16
#define NKT1  48
#define NKT2  16

// smem strides (elements)
#define SA  18    // A tile row stride (bf16)
#define SB  18    // B tile row stride, transposed [n][k] (bf16)
#define SH  264   // H1 row stride (bf16)  -> 132 words, %32==4 -> conflict-free frag loads
#define ST1 68    // T1 chunk row stride (float)
#define ST2 132   // T2 row stride (float)

// smem byte offsets
#define OFF_AHI   0
#define OFF_ALO   4608
#define OFF_BHI   9216
#define OFF_BLO   18432
#define OFF_T1C   27648
#define OFF_H1HI  62464      // also aliased as T2 (float [128][132]) after GEMM2
#define OFF_H1LO  130048
#define OFF_ADJW  197632
#define OFF_ADJI  199424
#define OFF_DINV  201216
#define OFF_POOL  201472
#define SMEM_BYTES 202496

__device__ __forceinline__ void mma_bf16(float* c, const unsigned* a, const unsigned* b) {
    asm volatile(
        "mma.sync.aligned.m16n8k16.row.col.f32.bf16.bf16.f32 "
        "{%0,%1,%2,%3}, {%4,%5,%6,%7}, {%8,%9}, {%0,%1,%2,%3};\n"
        : "+f"(c[0]), "+f"(c[1]), "+f"(c[2]), "+f"(c[3])
        : "r"(a[0]), "r"(a[1]), "r"(a[2]), "r"(a[3]), "r"(b[0]), "r"(b[1]));
}

// split two floats into packed (hi,hi) and (lo,lo) bf16x2 words (elem0 in low half)
__device__ __forceinline__ void split2(float a, float b, unsigned& hi, unsigned& lo) {
    __nv_bfloat16 ah = __float2bfloat16(a), bh = __float2bfloat16(b);
    float ar = a - __bfloat162float(ah);
    float br = b - __bfloat162float(bh);
    __nv_bfloat16 al = __float2bfloat16(ar), bl = __float2bfloat16(br);
    hi = ((unsigned)__bfloat16_as_ushort(bh) << 16) | (unsigned)__bfloat16_as_ushort(ah);
    lo = ((unsigned)__bfloat16_as_ushort(bl) << 16) | (unsigned)__bfloat16_as_ushort(al);
}

__global__ void __launch_bounds__(TPB, 1)
gnn_fused(const float* __restrict__ x,  const float* __restrict__ W1,
          const float* __restrict__ b1, const float* __restrict__ W2,
          const float* __restrict__ b2, const float* __restrict__ Wf,
          const float* __restrict__ bf, float* __restrict__ out)
{
    extern __shared__ unsigned char smem[];
    __nv_bfloat16* Ahi  = (__nv_bfloat16*)(smem + OFF_AHI);
    __nv_bfloat16* Alo  = (__nv_bfloat16*)(smem + OFF_ALO);
    __nv_bfloat16* Bhi  = (__nv_bfloat16*)(smem + OFF_BHI);
    __nv_bfloat16* Blo  = (__nv_bfloat16*)(smem + OFF_BLO);
    float*         T1c  = (float*)(smem + OFF_T1C);
    __nv_bfloat16* H1hi = (__nv_bfloat16*)(smem + OFF_H1HI);
    __nv_bfloat16* H1lo = (__nv_bfloat16*)(smem + OFF_H1LO);
    float*         adjw = (float*)(smem + OFF_ADJW);
    int*           adji = (int*)(smem + OFF_ADJI);
    float*         dinv = (float*)(smem + OFF_DINV);
    float*         pooled = (float*)(smem + OFF_POOL);

    const int tid  = threadIdx.x;
    const int lane = tid & 31;
    const int wid  = tid >> 5;
    const int wm   = wid >> 1;   // 0..7  (m16 tile row)
    const int wn   = wid & 1;    // 0..1  (n128 half for GEMM1, n64 half for GEMM2)
    const int tr   = lane >> 2;
    const int tc   = lane & 3;
    const int b0   = blockIdx.x * BT;

    // ---- build normalized adjacency (exact fp32, sparse, <=9 nbrs) ----
    if (tid < NNODE) {
        int r = tid / 7, c = tid % 7;
        int nr = min(r + 1, 6) - max(r - 1, 0) + 1;
        int nc = min(c + 1, 6) - max(c - 1, 0) + 1;
        dinv[tid] = 1.0f / sqrtf((float)(nr * nc));
    }
    __syncthreads();
    if (tid < NNODE) {
        int r = tid / 7, c = tid % 7;
        float di = dinv[tid];
        int t = 0;
        for (int dr = -1; dr <= 1; dr++)
            for (int dc = -1; dc <= 1; dc++) {
                int rr = r + dr, cc = c + dc;
                if (rr >= 0 && rr < 7 && cc >= 0 && cc < 7) {
                    int j = rr * 7 + cc;
                    adji[tid * 9 + t] = j;
                    adjw[tid * 9 + t] = di * dinv[j];
                    t++;
                }
            }
        for (; t < 9; t++) { adji[tid * 9 + t] = 0; adjw[tid * 9 + t] = 0.0f; }
    }

    // =========== GEMM1: T1 = X @ W1   (128 x 256 x 768, bf16x3) ===========
    float acc[16][4];
    #pragma unroll
    for (int j = 0; j < 16; j++)
        #pragma unroll
        for (int k = 0; k < 4; k++) acc[j][k] = 0.0f;

    const int arow  = tid >> 2;          // 0..127
    const int aquad = tid & 3;           // 0..3 (float4 within 16-wide k tile)
    const int ag    = arow >> 6;
    const int anode = arow & 63;
    const bool avalid = (anode < NNODE);
    const float* aptr = x + ((size_t)(b0 + ag) * NNODE + anode) * DIM + aquad * 4;

    const int bk0 = tid >> 6,        bn0 = (tid & 63) * 4;
    const int f1  = tid + TPB;
    const int bk1 = f1 >> 6,         bn1 = (f1 & 63) * 4;

    float4 aReg  = avalid ? *(const float4*)(aptr) : make_float4(0.f, 0.f, 0.f, 0.f);
    float4 bReg0 = *(const float4*)(W1 + (size_t)bk0 * C1 + bn0);
    float4 bReg1 = *(const float4*)(W1 + (size_t)bk1 * C1 + bn1);

    // store tile kt=0
    {
        unsigned h01, l01, h23, l23;
        split2(aReg.x, aReg.y, h01, l01);
        split2(aReg.z, aReg.w, h23, l23);
        unsigned* pA = (unsigned*)(Ahi + arow * SA + aquad * 4);
        pA[0] = h01; pA[1] = h23;
        unsigned* pL = (unsigned*)(Alo + arow * SA + aquad * 4);
        pL[0] = l01; pL[1] = l23;
        float v0[4] = { bReg0.x, bReg0.y, bReg0.z, bReg0.w };
        float v1[4] = { bReg1.x, bReg1.y, bReg1.z, bReg1.w };
        #pragma unroll
        for (int j = 0; j < 4; j++) {
            __nv_bfloat16 h = __float2bfloat16(v0[j]);
            Bhi[(bn0 + j) * SB + bk0] = h;
            Blo[(bn0 + j) * SB + bk0] = __float2bfloat16(v0[j] - __bfloat162float(h));
            __nv_bfloat16 g = __float2bfloat16(v1[j]);
            Bhi[(bn1 + j) * SB + bk1] = g;
            Blo[(bn1 + j) * SB + bk1] = __float2bfloat16(v1[j] - __bfloat162float(g));
        }
    }
    __syncthreads();

    #pragma unroll 1
    for (int kt = 0; kt < NKT1; kt++) {
        const bool more = (kt + 1 < NKT1);
        if (more) {
            aReg  = avalid ? *(const float4*)(aptr + (size_t)(kt + 1) * KT)
                           : make_float4(0.f, 0.f, 0.f, 0.f);
            bReg0 = *(const float4*)(W1 + (size_t)((kt + 1) * KT + bk0) * C1 + bn0);
            bReg1 = *(const float4*)(W1 + (size_t)((kt + 1) * KT + bk1) * C1 + bn1);
        }
        // A fragments (one m16 tile per warp)
        unsigned afh[4], afl[4];
        {
            const int row = wm * 16 + tr;
            const __nv_bfloat16* p = Ahi + row * SA + tc * 2;
            afh[0] = *(const unsigned*)(p);
            afh[1] = *(const unsigned*)(p + 8 * SA);
            afh[2] = *(const unsigned*)(p + 8);
            afh[3] = *(const unsigned*)(p + 8 * SA + 8);
            const __nv_bfloat16* q = Alo + row * SA + tc * 2;
            afl[0] = *(const unsigned*)(q);
            afl[1] = *(const unsigned*)(q + 8 * SA);
            afl[2] = *(const unsigned*)(q + 8);
            afl[3] = *(const unsigned*)(q + 8 * SA + 8);
        }
        #pragma unroll
        for (int nj = 0; nj < 16; nj++) {
            const int n = wn * 128 + nj * 8 + tr;
            const __nv_bfloat16* pb = Bhi + n * SB + tc * 2;
            unsigned bh[2] = { *(const unsigned*)(pb), *(const unsigned*)(pb + 8) };
            const __nv_bfloat16* ql = Blo + n * SB + tc * 2;
            unsigned bl[2] = { *(const unsigned*)(ql), *(const unsigned*)(ql + 8) };
            mma_bf16(acc[nj], afh, bh);
            mma_bf16(acc[nj], afh, bl);
            mma_bf16(acc[nj], afl, bh);
        }
        __syncthreads();
        if (more) {
            unsigned h01, l01, h23, l23;
            split2(aReg.x, aReg.y, h01, l01);
            split2(aReg.z, aReg.w, h23, l23);
            unsigned* pA = (unsigned*)(Ahi + arow * SA + aquad * 4);
            pA[0] = h01; pA[1] = h23;
            unsigned* pL = (unsigned*)(Alo + arow * SA + aquad * 4);
            pL[0] = l01; pL[1] = l23;
            float v0[4] = { bReg0.x, bReg0.y, bReg0.z, bReg0.w };
            float v1[4] = { bReg1.x, bReg1.y, bReg1.z, bReg1.w };
            #pragma unroll
            for (int j = 0; j < 4; j++) {
                __nv_bfloat16 h = __float2bfloat16(v0[j]);
                Bhi[(bn0 + j) * SB + bk0] = h;
                Blo[(bn0 + j) * SB + bk0] = __float2bfloat16(v0[j] - __bfloat162float(h));
                __nv_bfloat16 g = __float2bfloat16(v1[j]);
                Bhi[(bn1 + j) * SB + bk1] = g;
                Blo[(bn1 + j) * SB + bk1] = __float2bfloat16(v1[j] - __bfloat162float(g));
            }
        }
        __syncthreads();
    }

    // ===== epilogue 1 (chunked): H1 = relu(ADJ @ T1 + b1), split to bf16 hi/lo =====
    #pragma unroll 1
    for (int ci = 0; ci < 4; ci++) {
        __syncthreads();
        if ((ci >> 1) == wn) {
            const int njb = (ci & 1) * 8;
            #pragma unroll
            for (int nj2 = 0; nj2 < 8; nj2++) {
                const int nj  = njb + nj2;
                const int row = wm * 16 + tr;
                const int col = nj2 * 8 + tc * 2;
                T1c[row * ST1 + col]           = acc[nj][0];
                T1c[row * ST1 + col + 1]       = acc[nj][1];
                T1c[(row + 8) * ST1 + col]     = acc[nj][2];
                T1c[(row + 8) * ST1 + col + 1] = acc[nj][3];
            }
        }
        __syncthreads();
        for (int task = tid; task < 2 * NNODE * 64; task += TPB) {
            const int cl   = task & 63;
            const int rest = task >> 6;                  // 0..97
            const int g    = (rest >= NNODE) ? 1 : 0;
            const int i    = rest - g * NNODE;
            const int cg   = ci * 64 + cl;
            float s = b1[cg];
            #pragma unroll
            for (int t = 0; t < 9; t++)
                s += adjw[i * 9 + t] * T1c[(g * PADN + adji[i * 9 + t]) * ST1 + cl];
            s = fmaxf(s, 0.0f);
            __nv_bfloat16 h = __float2bfloat16(s);
            H1hi[(g * PADN + i) * SH + cg] = h;
            H1lo[(g * PADN + i) * SH + cg] = __float2bfloat16(s - __bfloat162float(h));
        }
    }

    // =========== GEMM2: T2 = H1 @ W2   (128 x 128 x 256, bf16x3) ===========
    #pragma unroll
    for (int j = 0; j < 8; j++)
        #pragma unroll
        for (int k = 0; k < 4; k++) acc[j][k] = 0.0f;

    const int ck = tid >> 5;            // 0..15
    const int cn = (tid & 31) * 4;      // 0..124
    float4 c2reg = *(const float4*)(W2 + (size_t)ck * C2 + cn);
    __syncthreads();
    {
        float v[4] = { c2reg.x, c2reg.y, c2reg.z, c2reg.w };
        #pragma unroll
        for (int j = 0; j < 4; j++) {
            __nv_bfloat16 h = __float2bfloat16(v[j]);
            Bhi[(cn + j) * SB + ck] = h;
            Blo[(cn + j) * SB + ck] = __float2bfloat16(v[j] - __bfloat162float(h));
        }
    }
    __syncthreads();

    #pragma unroll 1
    for (int kt = 0; kt < NKT2; kt++) {
        const bool more = (kt + 1 < NKT2);
        if (more) c2reg = *(const float4*)(W2 + (size_t)((kt + 1) * KT + ck) * C2 + cn);
        unsigned afh[4], afl[4];
        {
            const int row = wm * 16 + tr;
            const __nv_bfloat16* p = H1hi + row * SH + kt * KT + tc * 2;
            afh[0] = *(const unsigned*)(p);
            afh[1] = *(const unsigned*)(p + 8 * SH);
            afh[2] = *(const unsigned*)(p + 8);
            afh[3] = *(const unsigned*)(p + 8 * SH + 8);
            const __nv_bfloat16* q = H1lo + row * SH + kt * KT + tc * 2;
            afl[0] = *(const unsigned*)(q);
            afl[1] = *(const unsigned*)(q + 8 * SH);
            afl[2] = *(const unsigned*)(q + 8);
            afl[3] = *(const unsigned*)(q + 8 * SH + 8);
        }
        #pragma unroll
        for (int nj = 0; nj < 8; nj++) {
            const int n = wn * 64 + nj * 8 + tr;
            const __nv_bfloat16* pb = Bhi + n * SB + tc * 2;
            unsigned bh[2] = { *(const unsigned*)(pb), *(const unsigned*)(pb + 8) };
            const __nv_bfloat16* ql = Blo + n * SB + tc * 2;
            unsigned bl[2] = { *(const unsigned*)(ql), *(const unsigned*)(ql + 8) };
            mma_bf16(acc[nj], afh, bh);
            mma_bf16(acc[nj], afh, bl);
            mma_bf16(acc[nj], afl, bh);
        }
        __syncthreads();
        if (more) {
            float v[4] = { c2reg.x, c2reg.y, c2reg.z, c2reg.w };
            #pragma unroll
            for (int j = 0; j < 4; j++) {
                __nv_bfloat16 h = __float2bfloat16(v[j]);
                Bhi[(cn + j) * SB + ck] = h;
                Blo[(cn + j) * SB + ck] = __float2bfloat16(v[j] - __bfloat162float(h));
            }
        }
        __syncthreads();
    }

    // ===== epilogue 2: T2 -> ADJ + bias + relu + mean pool -> head =====
    float* T2 = (float*)(smem + OFF_H1HI);   // alias: H1hi no longer needed
    #pragma unroll
    for (int nj = 0; nj < 8; nj++) {
        const int row = wm * 16 + tr;
        const int col = wn * 64 + nj * 8 + tc * 2;
        T2[row * ST2 + col]           = acc[nj][0];
        T2[row * ST2 + col + 1]       = acc[nj][1];
        T2[(row + 8) * ST2 + col]     = acc[nj][2];
        T2[(row + 8) * ST2 + col + 1] = acc[nj][3];
    }
    __syncthreads();

    if (tid < BT * C2) {
        const int g = tid >> 7, c = tid & 127;
        const float bias = b2[c];
        float ps = 0.0f;
        for (int i = 0; i < NNODE; i++) {
            float s = bias;
            #pragma unroll
            for (int t = 0; t < 9; t++)
                s += adjw[i * 9 + t] * T2[(g * PADN + adji[i * 9 + t]) * ST2 + c];
            ps += fmaxf(s, 0.0f);
        }
        pooled[tid] = ps / 49.0f;
    }
    __syncthreads();

    if (tid < BT * NCLS) {
        const int g = tid / NCLS, o = tid - g * NCLS;
        float s = bf[o];
        const float* pp = pooled + g * C2;
        #pragma unroll 8
        for (int k = 0; k < C2; k++) s += pp[k] * Wf[k * NCLS + o];
        out[(size_t)(b0 + g) * NCLS + o] = s;
    }
}

extern "C" void kernel_launch(void* const* d_in, const int* in_sizes, int n_in,
                              void* d_out, int out_size)
{
    const float* x  = (const float*)d_in[0];
    const float* W1 = (const float*)d_in[1];
    const float* b1 = (const float*)d_in[2];
    const float* W2 = (const float*)d_in[3];
    const float* b2 = (const float*)d_in[4];
    const float* Wf = (const float*)d_in[5];
    const float* bf = (const float*)d_in[6];
    float* out = (float*)d_out;

    const int B = in_sizes[0] / (NNODE * DIM);   // 4096
    cudaFuncSetAttribute(gnn_fused, cudaFuncAttributeMaxDynamicSharedMemorySize, SMEM_BYTES);
    gnn_fused<<<B / BT, TPB, SMEM_BYTES>>>(x, W1, b1, W2, b2, Wf, bf, out);
}

// round 5
// speedup vs baseline: 1.6940x; 1.6940x over previous
#include <cuda_runtime.h>
#include <cuda_bf16.h>
#include <stdint.h>

#define TPB   512
#define NNODE 49
#define BT    2
#define DIM   768
#define C1    256
#define C2    128
#define NCLS  13
#define KT    16
#define NKT1  48
#define NKT2  16

#define SA 18     // A tile row stride (bf16 elems)
#define SB 24     // B tile row stride (bf16 elems) -> 48B rows: conflict-free frags + 16B-aligned staging
#define SH 264    // H1 row stride (bf16 elems)
#define D1S_STRIDE 65

// ---- stage layout (GEMM1 double buffer), byte offsets within a stage ----
#define OFF_AHI 0
#define OFF_ALO 4608
#define OFF_BHI 9216
#define OFF_BLO 21504
#define STG_BYTES 33792      // two stages: [0, 67584)

// ---- phase-2 layout (aliases GEMM1 stages; GEMM1 fully retired first) ----
#define OFF_H1HI 0           // 128 x 264 bf16 = 67584
#define OFF_H1LO 67584       // 67584
#define OFF_D1S  135168      // 128 x 65 fp32 = 33280
#define OFF_B2   168448      // 2 stages x (B2hi 6144 + B2lo 6144) = 24576
#define B2_STG   12288
// ---- persistent misc ----
#define OFF_ADJW 193024
#define OFF_ADJI 194816
#define OFF_DINV 196608
#define OFF_POOL 196864
#define SMEM_BYTES 197888

// ---- pre-split weights: [N][K] K-major bf16 hi/lo ----
__device__ __nv_bfloat16 g_W1hi[C1 * DIM];
__device__ __nv_bfloat16 g_W1lo[C1 * DIM];
__device__ __nv_bfloat16 g_W2hi[C2 * C1];
__device__ __nv_bfloat16 g_W2lo[C2 * C1];

__device__ __forceinline__ void mma_bf16(float* c, const unsigned* a, const unsigned* b) {
    asm volatile(
        "mma.sync.aligned.m16n8k16.row.col.f32.bf16.bf16.f32 "
        "{%0,%1,%2,%3}, {%4,%5,%6,%7}, {%8,%9}, {%0,%1,%2,%3};\n"
        : "+f"(c[0]), "+f"(c[1]), "+f"(c[2]), "+f"(c[3])
        : "r"(a[0]), "r"(a[1]), "r"(a[2]), "r"(a[3]), "r"(b[0]), "r"(b[1]));
}

__device__ __forceinline__ void split2(float a, float b, unsigned& hi, unsigned& lo) {
    __nv_bfloat16 ah = __float2bfloat16(a), bh = __float2bfloat16(b);
    float ar = a - __bfloat162float(ah);
    float br = b - __bfloat162float(bh);
    __nv_bfloat16 al = __float2bfloat16(ar), bl = __float2bfloat16(br);
    hi = ((unsigned)__bfloat16_as_ushort(bh) << 16) | (unsigned)__bfloat16_as_ushort(ah);
    lo = ((unsigned)__bfloat16_as_ushort(bl) << 16) | (unsigned)__bfloat16_as_ushort(al);
}

// ==================== prep: split + transpose weights ====================
__global__ void prep_weights(const float* __restrict__ W1, const float* __restrict__ W2) {
    int idx = blockIdx.x * blockDim.x + threadIdx.x;
    if (idx < C1 * DIM) {                       // W1 [768][256] -> [256][768]
        int k = idx >> 8, n = idx & 255;
        float v = W1[idx];
        __nv_bfloat16 h = __float2bfloat16(v);
        g_W1hi[n * DIM + k] = h;
        g_W1lo[n * DIM + k] = __float2bfloat16(v - __bfloat162float(h));
    } else if (idx < C1 * DIM + C1 * C2) {      // W2 [256][128] -> [128][256]
        int j = idx - C1 * DIM;
        int k = j >> 7, n = j & 127;
        float v = W2[j];
        __nv_bfloat16 h = __float2bfloat16(v);
        g_W2hi[n * C1 + k] = h;
        g_W2lo[n * C1 + k] = __float2bfloat16(v - __bfloat162float(h));
    }
}

// =========================== main fused kernel ===========================
__global__ void __launch_bounds__(TPB, 1)
gnn_fused(const float* __restrict__ x,  const float* __restrict__ b1,
          const float* __restrict__ b2, const float* __restrict__ Wf,
          const float* __restrict__ bf, float* __restrict__ out)
{
    extern __shared__ unsigned char smem[];
    float* adjw   = (float*)(smem + OFF_ADJW);
    int*   adji   = (int*)(smem + OFF_ADJI);
    float* dinv   = (float*)(smem + OFF_DINV);
    float* pooled = (float*)(smem + OFF_POOL);
    float* d1s    = (float*)(smem + OFF_D1S);

    const int tid  = threadIdx.x;
    const int lane = tid & 31;
    const int wid  = tid >> 5;
    const int wm   = wid & 3;    // m32 block (GEMM1 & GEMM2)
    const int wn   = wid >> 2;   // n64 block (GEMM1) / n32 block (GEMM2)
    const int tr   = lane >> 2;
    const int tc   = lane & 3;
    const int b0   = blockIdx.x * BT;

    // ---- adjacency tables (exact fp32) ----
    if (tid < NNODE) {
        int r = tid / 7, c = tid % 7;
        int nr = min(r + 1, 6) - max(r - 1, 0) + 1;
        int nc = min(c + 1, 6) - max(c - 1, 0) + 1;
        dinv[tid] = 1.0f / sqrtf((float)(nr * nc));
    }
    __syncthreads();
    if (tid < NNODE) {
        int r = tid / 7, c = tid % 7;
        float di = dinv[tid];
        int t = 0;
        for (int dr = -1; dr <= 1; dr++)
            for (int dc = -1; dc <= 1; dc++) {
                int rr = r + dr, cc = c + dc;
                if (rr >= 0 && rr < 7 && cc >= 0 && cc < 7) {
                    int j = rr * 7 + cc;
                    adji[tid * 9 + t] = j;
                    adjw[tid * 9 + t] = di * dinv[j];
                    t++;
                }
            }
        for (; t < 9; t++) { adji[tid * 9 + t] = 0; adjw[tid * 9 + t] = 0.0f; }
    }

    // =========== GEMM1: T1 = X @ W1   (128 x 256 x 768, bf16x3) ===========
    float acc[16][4];                 // [mi*8+nj][4], warp tile m32 x n64
    #pragma unroll
    for (int j = 0; j < 16; j++)
        #pragma unroll
        for (int k = 0; k < 4; k++) acc[j][k] = 0.0f;

    const int arow  = tid >> 2;           // 0..127
    const int aq    = tid & 3;            // float4 slot within k16
    const int ag    = arow >> 6;
    const int anode = arow & 63;
    const bool aval = (anode < NNODE);
    const float* px = x + ((size_t)(b0 + ag) * NNODE + anode) * DIM + aq * 4;

    const int bn  = tid >> 1;             // 0..255
    const int bk0 = (tid & 1) * 8;        // 8 bf16 per uint4
    const __nv_bfloat16* pW1h = g_W1hi + (size_t)bn * DIM + bk0;
    const __nv_bfloat16* pW1l = g_W1lo + (size_t)bn * DIM + bk0;

    // --- prologue: stage kt=0 into buf0, prefetch kt=1 into regs ---
    {
        float4 a0 = aval ? *(const float4*)(px) : make_float4(0.f,0.f,0.f,0.f);
        unsigned h01,l01,h23,l23;
        split2(a0.x, a0.y, h01, l01); split2(a0.z, a0.w, h23, l23);
        __nv_bfloat16* Ah = (__nv_bfloat16*)(smem + OFF_AHI);
        __nv_bfloat16* Al = (__nv_bfloat16*)(smem + OFF_ALO);
        unsigned* pA = (unsigned*)(Ah + arow*SA + aq*4);  pA[0]=h01; pA[1]=h23;
        unsigned* pL = (unsigned*)(Al + arow*SA + aq*4);  pL[0]=l01; pL[1]=l23;
        uint4 bh = *(const uint4*)(pW1h);
        uint4 bl = *(const uint4*)(pW1l);
        *(uint4*)((__nv_bfloat16*)(smem + OFF_BHI) + bn*SB + bk0) = bh;
        *(uint4*)((__nv_bfloat16*)(smem + OFF_BLO) + bn*SB + bk0) = bl;
    }
    float4 aNext = aval ? *(const float4*)(px + KT) : make_float4(0.f,0.f,0.f,0.f);
    uint4  bhNext = *(const uint4*)(pW1h + KT);
    uint4  blNext = *(const uint4*)(pW1l + KT);
    __syncthreads();

    #pragma unroll 1
    for (int kt = 0; kt < NKT1; kt++) {
        const uint32_t cs = (uint32_t)(kt & 1) * STG_BYTES;
        const uint32_t ns = (uint32_t)((kt + 1) & 1) * STG_BYTES;
        const __nv_bfloat16* Ah = (const __nv_bfloat16*)(smem + cs + OFF_AHI);
        const __nv_bfloat16* Al = (const __nv_bfloat16*)(smem + cs + OFF_ALO);
        const __nv_bfloat16* Bh = (const __nv_bfloat16*)(smem + cs + OFF_BHI);
        const __nv_bfloat16* Bl = (const __nv_bfloat16*)(smem + cs + OFF_BLO);

        unsigned afh[2][4], afl[2][4];
        #pragma unroll
        for (int mi = 0; mi < 2; mi++) {
            const int row = wm*32 + mi*16 + tr;
            const __nv_bfloat16* p = Ah + row*SA + tc*2;
            afh[mi][0] = *(const unsigned*)(p);
            afh[mi][1] = *(const unsigned*)(p + 8*SA);
            afh[mi][2] = *(const unsigned*)(p + 8);
            afh[mi][3] = *(const unsigned*)(p + 8*SA + 8);
            const __nv_bfloat16* q = Al + row*SA + tc*2;
            afl[mi][0] = *(const unsigned*)(q);
            afl[mi][1] = *(const unsigned*)(q + 8*SA);
            afl[mi][2] = *(const unsigned*)(q + 8);
            afl[mi][3] = *(const unsigned*)(q + 8*SA + 8);
        }
        #pragma unroll
        for (int nj = 0; nj < 8; nj++) {
            const int n = wn*64 + nj*8 + tr;
            const __nv_bfloat16* pb = Bh + n*SB + tc*2;
            unsigned bh[2] = { *(const unsigned*)(pb), *(const unsigned*)(pb + 8) };
            const __nv_bfloat16* ql = Bl + n*SB + tc*2;
            unsigned bl[2] = { *(const unsigned*)(ql), *(const unsigned*)(ql + 8) };
            #pragma unroll
            for (int mi = 0; mi < 2; mi++) {
                mma_bf16(acc[mi*8+nj], afh[mi], bh);
                mma_bf16(acc[mi*8+nj], afh[mi], bl);
                mma_bf16(acc[mi*8+nj], afl[mi], bh);
            }
        }
        if (kt + 1 < NKT1) {
            unsigned h01,l01,h23,l23;
            split2(aNext.x, aNext.y, h01, l01); split2(aNext.z, aNext.w, h23, l23);
            __nv_bfloat16* Ahn = (__nv_bfloat16*)(smem + ns + OFF_AHI);
            __nv_bfloat16* Aln = (__nv_bfloat16*)(smem + ns + OFF_ALO);
            unsigned* pA = (unsigned*)(Ahn + arow*SA + aq*4); pA[0]=h01; pA[1]=h23;
            unsigned* pL = (unsigned*)(Aln + arow*SA + aq*4); pL[0]=l01; pL[1]=l23;
            *(uint4*)((__nv_bfloat16*)(smem + ns + OFF_BHI) + bn*SB + bk0) = bhNext;
            *(uint4*)((__nv_bfloat16*)(smem + ns + OFF_BLO) + bn*SB + bk0) = blNext;
            if (kt + 2 < NKT1) {
                aNext  = aval ? *(const float4*)(px + (size_t)(kt+2)*KT)
                              : make_float4(0.f,0.f,0.f,0.f);
                bhNext = *(const uint4*)(pW1h + (size_t)(kt+2)*KT);
                blNext = *(const uint4*)(pW1l + (size_t)(kt+2)*KT);
            }
        }
        __syncthreads();
    }

    // ===== epilogue 1 (chunked): H1 = relu(ADJ @ T1 + b1), split bf16 hi/lo =====
    __nv_bfloat16* H1hi = (__nv_bfloat16*)(smem + OFF_H1HI);
    __nv_bfloat16* H1lo = (__nv_bfloat16*)(smem + OFF_H1LO);
    #pragma unroll 1
    for (int ci = 0; ci < 4; ci++) {
        if (wn == ci) {
            #pragma unroll
            for (int mi = 0; mi < 2; mi++)
                #pragma unroll
                for (int nj = 0; nj < 8; nj++) {
                    const int row = wm*32 + mi*16 + tr;
                    const int col = nj*8 + tc*2;
                    float* a = acc[mi*8+nj];
                    d1s[row * D1S_STRIDE + col]           = a[0];
                    d1s[row * D1S_STRIDE + col + 1]       = a[1];
                    d1s[(row + 8) * D1S_STRIDE + col]     = a[2];
                    d1s[(row + 8) * D1S_STRIDE + col + 1] = a[3];
                }
        }
        __syncthreads();
        for (int task = tid; task < 2 * NNODE * 64; task += TPB) {
            const int cl   = task & 63;
            const int rest = task >> 6;
            const int g    = (rest >= NNODE) ? 1 : 0;
            const int i    = rest - g * NNODE;
            float s = __ldg(&b1[ci * 64 + cl]);
            #pragma unroll
            for (int t = 0; t < 9; t++)
                s += adjw[i*9+t] * d1s[(g*64 + adji[i*9+t]) * D1S_STRIDE + cl];
            s = fmaxf(s, 0.0f);
            __nv_bfloat16 h = __float2bfloat16(s);
            H1hi[(g*64 + i) * SH + ci*64 + cl] = h;
            H1lo[(g*64 + i) * SH + ci*64 + cl] = __float2bfloat16(s - __bfloat162float(h));
        }
        __syncthreads();
    }

    // =========== GEMM2: T2 = H1 @ W2   (128 x 128 x 256, bf16x3) ===========
    float acc2[8][4];                 // [mi*4+nj][4], warp tile m32 x n32
    #pragma unroll
    for (int j = 0; j < 8; j++)
        #pragma unroll
        for (int k = 0; k < 4; k++) acc2[j][k] = 0.0f;

    const int cn  = tid >> 2;             // 0..127
    const int cq  = tid & 3;              // uint2 slot
    const __nv_bfloat16* pW2h = g_W2hi + (size_t)cn * C1 + cq * 4;
    const __nv_bfloat16* pW2l = g_W2lo + (size_t)cn * C1 + cq * 4;
    {
        uint2 bh = *(const uint2*)(pW2h);
        uint2 bl = *(const uint2*)(pW2l);
        *(uint2*)((__nv_bfloat16*)(smem + OFF_B2) + cn*SB + cq*4) = bh;
        *(uint2*)((__nv_bfloat16*)(smem + OFF_B2 + 6144) + cn*SB + cq*4) = bl;
    }
    uint2 chNext = *(const uint2*)(pW2h + KT);
    uint2 clNext = *(const uint2*)(pW2l + KT);
    __syncthreads();

    #pragma unroll 1
    for (int kt = 0; kt < NKT2; kt++) {
        const uint32_t cs = OFF_B2 + (uint32_t)(kt & 1) * B2_STG;
        const uint32_t ns = OFF_B2 + (uint32_t)((kt + 1) & 1) * B2_STG;
        const __nv_bfloat16* Bh = (const __nv_bfloat16*)(smem + cs);
        const __nv_bfloat16* Bl = (const __nv_bfloat16*)(smem + cs + 6144);

        unsigned afh[2][4], afl[2][4];
        #pragma unroll
        for (int mi = 0; mi < 2; mi++) {
            const int row = wm*32 + mi*16 + tr;
            const __nv_bfloat16* p = H1hi + row*SH + kt*KT + tc*2;
            afh[mi][0] = *(const unsigned*)(p);
            afh[mi][1] = *(const unsigned*)(p + 8*SH);
            afh[mi][2] = *(const unsigned*)(p + 8);
            afh[mi][3] = *(const unsigned*)(p + 8*SH + 8);
            const __nv_bfloat16* q = H1lo + row*SH + kt*KT + tc*2;
            afl[mi][0] = *(const unsigned*)(q);
            afl[mi][1] = *(const unsigned*)(q + 8*SH);
            afl[mi][2] = *(const unsigned*)(q + 8);
            afl[mi][3] = *(const unsigned*)(q + 8*SH + 8);
        }
        #pragma unroll
        for (int nj = 0; nj < 4; nj++) {
            const int n = wn*32 + nj*8 + tr;
            const __nv_bfloat16* pb = Bh + n*SB + tc*2;
            unsigned bh[2] = { *(const unsigned*)(pb), *(const unsigned*)(pb + 8) };
            const __nv_bfloat16* ql = Bl + n*SB + tc*2;
            unsigned bl[2] = { *(const unsigned*)(ql), *(const unsigned*)(ql + 8) };
            #pragma unroll
            for (int mi = 0; mi < 2; mi++) {
                mma_bf16(acc2[mi*4+nj], afh[mi], bh);
                mma_bf16(acc2[mi*4+nj], afh[mi], bl);
                mma_bf16(acc2[mi*4+nj], afl[mi], bh);
            }
        }
        if (kt + 1 < NKT2) {
            *(uint2*)((__nv_bfloat16*)(smem + ns) + cn*SB + cq*4) = chNext;
            *(uint2*)((__nv_bfloat16*)(smem + ns + 6144) + cn*SB + cq*4) = clNext;
            if (kt + 2 < NKT2) {
                chNext = *(const uint2*)(pW2h + (size_t)(kt+2)*KT);
                clNext = *(const uint2*)(pW2l + (size_t)(kt+2)*KT);
            }
        }
        __syncthreads();
    }

    // ======== epilogue 2: ADJ + bias + relu + mean-pool + head ========
    #pragma unroll 1
    for (int ci = 0; ci < 2; ci++) {
        if ((wn >> 1) == ci) {
            #pragma unroll
            for (int mi = 0; mi < 2; mi++)
                #pragma unroll
                for (int nj = 0; nj < 4; nj++) {
                    const int row = wm*32 + mi*16 + tr;
                    const int col = (wn & 1)*32 + nj*8 + tc*2;
                    float* a = acc2[mi*4+nj];
                    d1s[row * D1S_STRIDE + col]           = a[0];
                    d1s[row * D1S_STRIDE + col + 1]       = a[1];
                    d1s[(row + 8) * D1S_STRIDE + col]     = a[2];
                    d1s[(row + 8) * D1S_STRIDE + col + 1] = a[3];
                }
        }
        __syncthreads();
        {
            const int quarter = tid & 3;
            const int rest    = tid >> 2;       // 0..127
            const int g       = rest >> 6;
            const int cl      = rest & 63;
            const float bias  = __ldg(&b2[ci * 64 + cl]);
            const int i0   = quarter * 13;
            const int icnt = (quarter < 3) ? 13 : 10;
            float ps = 0.0f;
            for (int ii = 0; ii < icnt; ii++) {
                const int i = i0 + ii;
                float s = bias;
                #pragma unroll
                for (int t = 0; t < 9; t++)
                    s += adjw[i*9+t] * d1s[(g*64 + adji[i*9+t]) * D1S_STRIDE + cl];
                ps += fmaxf(s, 0.0f);
            }
            ps += __shfl_xor_sync(0xFFFFFFFFu, ps, 1);
            ps += __shfl_xor_sync(0xFFFFFFFFu, ps, 2);
            if (quarter == 0) pooled[g * C2 + ci * 64 + cl] = ps * (1.0f / 49.0f);
        }
        __syncthreads();
    }

    if (tid < BT * NCLS) {
        const int g = tid / NCLS, o = tid - g * NCLS;
        float s = __ldg(&bf[o]);
        const float* pp = pooled + g * C2;
        #pragma unroll 8
        for (int k = 0; k < C2; k++) s += pp[k] * __ldg(&Wf[k * NCLS + o]);
        out[(size_t)(b0 + g) * NCLS + o] = s;
    }
}

extern "C" void kernel_launch(void* const* d_in, const int* in_sizes, int n_in,
                              void* d_out, int out_size)
{
    const float* x  = (const float*)d_in[0];
    const float* W1 = (const float*)d_in[1];
    const float* b1 = (const float*)d_in[2];
    const float* W2 = (const float*)d_in[3];
    const float* b2 = (const float*)d_in[4];
    const float* Wf = (const float*)d_in[5];
    const float* bf = (const float*)d_in[6];
    float* out = (float*)d_out;

    const int B = in_sizes[0] / (NNODE * DIM);   // 4096

    prep_weights<<<(C1 * DIM + C1 * C2 + 255) / 256, 256>>>(W1, W2);

    cudaFuncSetAttribute(gnn_fused, cudaFuncAttributeMaxDynamicSharedMemorySize, SMEM_BYTES);
    gnn_fused<<<B / BT, TPB, SMEM_BYTES>>>(x, b1, b2, Wf, bf, out);
}

// round 6
// speedup vs baseline: 1.7441x; 1.0295x over previous
#include <cuda_runtime.h>
#include <cuda_bf16.h>
#include <stdint.h>

#define TPB   256
#define NNODE 49
#define BT    2
#define DIM   768
#define C1    256
#define C2    128
#define NCLS  13
#define KT    16
#define NKT1  48
#define NKT2  16

#define SA 18     // A tile row stride (bf16 elems)
#define SB 24     // B tile row stride (bf16 elems) -> conflict-free frags, 16B-aligned staging
#define SH 264    // H1 row stride (bf16 elems)
#define D1S_STRIDE 65

// ---- stage layout (GEMM1 double buffer), byte offsets within a stage ----
#define OFF_AHI 0
#define OFF_ALO 4608
#define OFF_BHI 9216
#define OFF_BLO 21504
#define STG_BYTES 33792      // two stages: [0, 67584)

// ---- phase-2 layout (aliases GEMM1 stages; GEMM1 fully retired first) ----
#define OFF_H1HI 0           // 128 x 264 bf16 = 67584
#define OFF_H1LO 67584
#define OFF_D1S  135168      // 128 x 65 fp32 = 33280
#define OFF_B2   168448      // 2 stages x (B2hi 6144 + B2lo 6144)
#define B2_STG   12288
// ---- persistent misc ----
#define OFF_ADJW 193024
#define OFF_ADJI 194816
#define OFF_DINV 196608
#define OFF_POOL 196864
#define SMEM_BYTES 197888

// ---- pre-split weights: [N][K] K-major bf16 hi/lo ----
__device__ __nv_bfloat16 g_W1hi[C1 * DIM];
__device__ __nv_bfloat16 g_W1lo[C1 * DIM];
__device__ __nv_bfloat16 g_W2hi[C2 * C1];
__device__ __nv_bfloat16 g_W2lo[C2 * C1];

__device__ __forceinline__ void mma_bf16(float* c, const unsigned* a, const unsigned* b) {
    asm volatile(
        "mma.sync.aligned.m16n8k16.row.col.f32.bf16.bf16.f32 "
        "{%0,%1,%2,%3}, {%4,%5,%6,%7}, {%8,%9}, {%0,%1,%2,%3};\n"
        : "+f"(c[0]), "+f"(c[1]), "+f"(c[2]), "+f"(c[3])
        : "r"(a[0]), "r"(a[1]), "r"(a[2]), "r"(a[3]), "r"(b[0]), "r"(b[1]));
}

__device__ __forceinline__ void split2(float a, float b, unsigned& hi, unsigned& lo) {
    __nv_bfloat16 ah = __float2bfloat16(a), bh = __float2bfloat16(b);
    float ar = a - __bfloat162float(ah);
    float br = b - __bfloat162float(bh);
    __nv_bfloat16 al = __float2bfloat16(ar), bl = __float2bfloat16(br);
    hi = ((unsigned)__bfloat16_as_ushort(bh) << 16) | (unsigned)__bfloat16_as_ushort(ah);
    lo = ((unsigned)__bfloat16_as_ushort(bl) << 16) | (unsigned)__bfloat16_as_ushort(al);
}

// ==================== prep: split + transpose weights ====================
__global__ void prep_weights(const float* __restrict__ W1, const float* __restrict__ W2) {
    int idx = blockIdx.x * blockDim.x + threadIdx.x;
    if (idx < C1 * DIM) {                       // W1 [768][256] -> [256][768]
        int k = idx >> 8, n = idx & 255;
        float v = W1[idx];
        __nv_bfloat16 h = __float2bfloat16(v);
        g_W1hi[n * DIM + k] = h;
        g_W1lo[n * DIM + k] = __float2bfloat16(v - __bfloat162float(h));
    } else if (idx < C1 * DIM + C1 * C2) {      // W2 [256][128] -> [128][256]
        int j = idx - C1 * DIM;
        int k = j >> 7, n = j & 127;
        float v = W2[j];
        __nv_bfloat16 h = __float2bfloat16(v);
        g_W2hi[n * C1 + k] = h;
        g_W2lo[n * C1 + k] = __float2bfloat16(v - __bfloat162float(h));
    }
}

// =========================== main fused kernel ===========================
__global__ void __launch_bounds__(TPB, 1)
gnn_fused(const float* __restrict__ x,  const float* __restrict__ b1,
          const float* __restrict__ b2, const float* __restrict__ Wf,
          const float* __restrict__ bf, float* __restrict__ out)
{
    extern __shared__ unsigned char smem[];
    float* adjw   = (float*)(smem + OFF_ADJW);
    int*   adji   = (int*)(smem + OFF_ADJI);
    float* dinv   = (float*)(smem + OFF_DINV);
    float* pooled = (float*)(smem + OFF_POOL);
    float* d1s    = (float*)(smem + OFF_D1S);

    const int tid  = threadIdx.x;
    const int lane = tid & 31;
    const int wid  = tid >> 5;    // 0..7
    const int wm   = wid >> 2;    // 0..1  (m64 block)
    const int wn   = wid & 3;     // 0..3  (n64 block G1 / n32 block G2)
    const int tr   = lane >> 2;
    const int tc   = lane & 3;
    const int b0   = blockIdx.x * BT;

    // ---- adjacency tables (exact fp32) ----
    if (tid < NNODE) {
        int r = tid / 7, c = tid % 7;
        int nr = min(r + 1, 6) - max(r - 1, 0) + 1;
        int nc = min(c + 1, 6) - max(c - 1, 0) + 1;
        dinv[tid] = 1.0f / sqrtf((float)(nr * nc));
    }
    __syncthreads();
    if (tid < NNODE) {
        int r = tid / 7, c = tid % 7;
        float di = dinv[tid];
        int t = 0;
        for (int dr = -1; dr <= 1; dr++)
            for (int dc = -1; dc <= 1; dc++) {
                int rr = r + dr, cc = c + dc;
                if (rr >= 0 && rr < 7 && cc >= 0 && cc < 7) {
                    int j = rr * 7 + cc;
                    adji[tid * 9 + t] = j;
                    adjw[tid * 9 + t] = di * dinv[j];
                    t++;
                }
            }
        for (; t < 9; t++) { adji[tid * 9 + t] = 0; adjw[tid * 9 + t] = 0.0f; }
    }

    // =========== GEMM1: T1 = X @ W1  (128 x 256 x 768, bf16x3) ===========
    float acc[32][4];                 // [mi*8+nj], warp tile m64 x n64
    #pragma unroll
    for (int j = 0; j < 32; j++)
        #pragma unroll
        for (int k = 0; k < 4; k++) acc[j][k] = 0.0f;

    // staging slots: A -> 2 per thread, B -> 2 per thread
    int   arowA[2], aqA[2];
    bool  avalA[2];
    const float* pxA[2];
    int   bnB[2], bkB[2];
    const __nv_bfloat16 *pW1h[2], *pW1l[2];
    #pragma unroll
    for (int s2 = 0; s2 < 2; s2++) {
        const int sl = tid + s2 * TPB;
        arowA[s2] = sl >> 2;  aqA[s2] = sl & 3;
        const int ag = arowA[s2] >> 6, anode = arowA[s2] & 63;
        avalA[s2] = (anode < NNODE);
        pxA[s2] = x + ((size_t)(b0 + ag) * NNODE + anode) * DIM + aqA[s2] * 4;
        bnB[s2] = sl >> 1;  bkB[s2] = (sl & 1) * 8;
        pW1h[s2] = g_W1hi + (size_t)bnB[s2] * DIM + bkB[s2];
        pW1l[s2] = g_W1lo + (size_t)bnB[s2] * DIM + bkB[s2];
    }

    // --- prologue: stage kt=0 into buf0, prefetch kt=1 into regs ---
    #pragma unroll
    for (int s2 = 0; s2 < 2; s2++) {
        float4 a0 = avalA[s2] ? *(const float4*)(pxA[s2]) : make_float4(0.f,0.f,0.f,0.f);
        unsigned h01,l01,h23,l23;
        split2(a0.x, a0.y, h01, l01); split2(a0.z, a0.w, h23, l23);
        unsigned* pA = (unsigned*)((__nv_bfloat16*)(smem + OFF_AHI) + arowA[s2]*SA + aqA[s2]*4);
        pA[0]=h01; pA[1]=h23;
        unsigned* pL = (unsigned*)((__nv_bfloat16*)(smem + OFF_ALO) + arowA[s2]*SA + aqA[s2]*4);
        pL[0]=l01; pL[1]=l23;
        uint4 bh = *(const uint4*)(pW1h[s2]);
        uint4 bl = *(const uint4*)(pW1l[s2]);
        *(uint4*)((__nv_bfloat16*)(smem + OFF_BHI) + bnB[s2]*SB + bkB[s2]) = bh;
        *(uint4*)((__nv_bfloat16*)(smem + OFF_BLO) + bnB[s2]*SB + bkB[s2]) = bl;
    }
    float4 aN[2];  uint4 bhN[2], blN[2];
    #pragma unroll
    for (int s2 = 0; s2 < 2; s2++) {
        aN[s2]  = avalA[s2] ? *(const float4*)(pxA[s2] + KT) : make_float4(0.f,0.f,0.f,0.f);
        bhN[s2] = *(const uint4*)(pW1h[s2] + KT);
        blN[s2] = *(const uint4*)(pW1l[s2] + KT);
    }
    __syncthreads();

    #pragma unroll 1
    for (int kt = 0; kt < NKT1; kt++) {
        const uint32_t cs = (uint32_t)(kt & 1) * STG_BYTES;
        const uint32_t ns = (uint32_t)((kt + 1) & 1) * STG_BYTES;
        const __nv_bfloat16* Ah = (const __nv_bfloat16*)(smem + cs + OFF_AHI);
        const __nv_bfloat16* Al = (const __nv_bfloat16*)(smem + cs + OFF_ALO);
        const __nv_bfloat16* Bh = (const __nv_bfloat16*)(smem + cs + OFF_BHI);
        const __nv_bfloat16* Bl = (const __nv_bfloat16*)(smem + cs + OFF_BLO);

        unsigned afh[4][4], afl[4][4];
        #pragma unroll
        for (int mi = 0; mi < 4; mi++) {
            const int row = wm*64 + mi*16 + tr;
            const __nv_bfloat16* p = Ah + row*SA + tc*2;
            afh[mi][0] = *(const unsigned*)(p);
            afh[mi][1] = *(const unsigned*)(p + 8*SA);
            afh[mi][2] = *(const unsigned*)(p + 8);
            afh[mi][3] = *(const unsigned*)(p + 8*SA + 8);
            const __nv_bfloat16* q = Al + row*SA + tc*2;
            afl[mi][0] = *(const unsigned*)(q);
            afl[mi][1] = *(const unsigned*)(q + 8*SA);
            afl[mi][2] = *(const unsigned*)(q + 8);
            afl[mi][3] = *(const unsigned*)(q + 8*SA + 8);
        }
        #pragma unroll
        for (int nj = 0; nj < 8; nj++) {
            const int n = wn*64 + nj*8 + tr;
            const __nv_bfloat16* pb = Bh + n*SB + tc*2;
            unsigned bh[2] = { *(const unsigned*)(pb), *(const unsigned*)(pb + 8) };
            const __nv_bfloat16* ql = Bl + n*SB + tc*2;
            unsigned bl[2] = { *(const unsigned*)(ql), *(const unsigned*)(ql + 8) };
            #pragma unroll
            for (int mi = 0; mi < 4; mi++) {
                mma_bf16(acc[mi*8+nj], afh[mi], bh);
                mma_bf16(acc[mi*8+nj], afh[mi], bl);
                mma_bf16(acc[mi*8+nj], afl[mi], bh);
            }
        }
        if (kt + 1 < NKT1) {
            #pragma unroll
            for (int s2 = 0; s2 < 2; s2++) {
                unsigned h01,l01,h23,l23;
                split2(aN[s2].x, aN[s2].y, h01, l01);
                split2(aN[s2].z, aN[s2].w, h23, l23);
                unsigned* pA = (unsigned*)((__nv_bfloat16*)(smem + ns + OFF_AHI) + arowA[s2]*SA + aqA[s2]*4);
                pA[0]=h01; pA[1]=h23;
                unsigned* pL = (unsigned*)((__nv_bfloat16*)(smem + ns + OFF_ALO) + arowA[s2]*SA + aqA[s2]*4);
                pL[0]=l01; pL[1]=l23;
                *(uint4*)((__nv_bfloat16*)(smem + ns + OFF_BHI) + bnB[s2]*SB + bkB[s2]) = bhN[s2];
                *(uint4*)((__nv_bfloat16*)(smem + ns + OFF_BLO) + bnB[s2]*SB + bkB[s2]) = blN[s2];
            }
            if (kt + 2 < NKT1) {
                #pragma unroll
                for (int s2 = 0; s2 < 2; s2++) {
                    aN[s2]  = avalA[s2] ? *(const float4*)(pxA[s2] + (size_t)(kt+2)*KT)
                                        : make_float4(0.f,0.f,0.f,0.f);
                    bhN[s2] = *(const uint4*)(pW1h[s2] + (size_t)(kt+2)*KT);
                    blN[s2] = *(const uint4*)(pW1l[s2] + (size_t)(kt+2)*KT);
                }
            }
        }
        __syncthreads();
    }

    // ===== epilogue 1 (chunked): H1 = relu(ADJ @ T1 + b1), split bf16 hi/lo =====
    __nv_bfloat16* H1hi = (__nv_bfloat16*)(smem + OFF_H1HI);
    __nv_bfloat16* H1lo = (__nv_bfloat16*)(smem + OFF_H1LO);
    #pragma unroll 1
    for (int ci = 0; ci < 4; ci++) {
        if (wn == ci) {
            #pragma unroll
            for (int mi = 0; mi < 4; mi++)
                #pragma unroll
                for (int nj = 0; nj < 8; nj++) {
                    const int row = wm*64 + mi*16 + tr;
                    const int col = nj*8 + tc*2;
                    float* a = acc[mi*8+nj];
                    d1s[row * D1S_STRIDE + col]           = a[0];
                    d1s[row * D1S_STRIDE + col + 1]       = a[1];
                    d1s[(row + 8) * D1S_STRIDE + col]     = a[2];
                    d1s[(row + 8) * D1S_STRIDE + col + 1] = a[3];
                }
        }
        __syncthreads();
        for (int task = tid; task < 2 * NNODE * 64; task += TPB) {
            const int cl   = task & 63;
            const int rest = task >> 6;
            const int g    = (rest >= NNODE) ? 1 : 0;
            const int i    = rest - g * NNODE;
            float s = __ldg(&b1[ci * 64 + cl]);
            #pragma unroll
            for (int t = 0; t < 9; t++)
                s += adjw[i*9+t] * d1s[(g*64 + adji[i*9+t]) * D1S_STRIDE + cl];
            s = fmaxf(s, 0.0f);
            __nv_bfloat16 h = __float2bfloat16(s);
            H1hi[(g*64 + i) * SH + ci*64 + cl] = h;
            H1lo[(g*64 + i) * SH + ci*64 + cl] = __float2bfloat16(s - __bfloat162float(h));
        }
        __syncthreads();
    }

    // =========== GEMM2: T2 = H1 @ W2  (128 x 128 x 256, bf16x3) ===========
    float acc2[16][4];                // [mi*4+nj], warp tile m64 x n32
    #pragma unroll
    for (int j = 0; j < 16; j++)
        #pragma unroll
        for (int k = 0; k < 4; k++) acc2[j][k] = 0.0f;

    const int cn = tid >> 1;          // 0..127
    const int cq = tid & 1;           // 16B chunk within k16
    const __nv_bfloat16* pW2h = g_W2hi + (size_t)cn * C1 + cq * 8;
    const __nv_bfloat16* pW2l = g_W2lo + (size_t)cn * C1 + cq * 8;
    {
        uint4 bh = *(const uint4*)(pW2h);
        uint4 bl = *(const uint4*)(pW2l);
        *(uint4*)((__nv_bfloat16*)(smem + OFF_B2) + cn*SB + cq*8) = bh;
        *(uint4*)((__nv_bfloat16*)(smem + OFF_B2 + 6144) + cn*SB + cq*8) = bl;
    }
    uint4 chN = *(const uint4*)(pW2h + KT);
    uint4 clN = *(const uint4*)(pW2l + KT);
    __syncthreads();

    #pragma unroll 1
    for (int kt = 0; kt < NKT2; kt++) {
        const uint32_t cs = OFF_B2 + (uint32_t)(kt & 1) * B2_STG;
        const uint32_t ns = OFF_B2 + (uint32_t)((kt + 1) & 1) * B2_STG;
        const __nv_bfloat16* Bh = (const __nv_bfloat16*)(smem + cs);
        const __nv_bfloat16* Bl = (const __nv_bfloat16*)(smem + cs + 6144);

        unsigned afh[4][4], afl[4][4];
        #pragma unroll
        for (int mi = 0; mi < 4; mi++) {
            const int row = wm*64 + mi*16 + tr;
            const __nv_bfloat16* p = H1hi + row*SH + kt*KT + tc*2;
            afh[mi][0] = *(const unsigned*)(p);
            afh[mi][1] = *(const unsigned*)(p + 8*SH);
            afh[mi][2] = *(const unsigned*)(p + 8);
            afh[mi][3] = *(const unsigned*)(p + 8*SH + 8);
            const __nv_bfloat16* q = H1lo + row*SH + kt*KT + tc*2;
            afl[mi][0] = *(const unsigned*)(q);
            afl[mi][1] = *(const unsigned*)(q + 8*SH);
            afl[mi][2] = *(const unsigned*)(q + 8);
            afl[mi][3] = *(const unsigned*)(q + 8*SH + 8);
        }
        #pragma unroll
        for (int nj = 0; nj < 4; nj++) {
            const int n = wn*32 + nj*8 + tr;
            const __nv_bfloat16* pb = Bh + n*SB + tc*2;
            unsigned bh[2] = { *(const unsigned*)(pb), *(const unsigned*)(pb + 8) };
            const __nv_bfloat16* ql = Bl + n*SB + tc*2;
            unsigned bl[2] = { *(const unsigned*)(ql), *(const unsigned*)(ql + 8) };
            #pragma unroll
            for (int mi = 0; mi < 4; mi++) {
                mma_bf16(acc2[mi*4+nj], afh[mi], bh);
                mma_bf16(acc2[mi*4+nj], afh[mi], bl);
                mma_bf16(acc2[mi*4+nj], afl[mi], bh);
            }
        }
        if (kt + 1 < NKT2) {
            *(uint4*)((__nv_bfloat16*)(smem + ns) + cn*SB + cq*8) = chN;
            *(uint4*)((__nv_bfloat16*)(smem + ns + 6144) + cn*SB + cq*8) = clN;
            if (kt + 2 < NKT2) {
                chN = *(const uint4*)(pW2h + (size_t)(kt+2)*KT);
                clN = *(const uint4*)(pW2l + (size_t)(kt+2)*KT);
            }
        }
        __syncthreads();
    }

    // ======== epilogue 2: ADJ + bias + relu + mean-pool + head ========
    #pragma unroll 1
    for (int ci = 0; ci < 2; ci++) {
        if ((wn >> 1) == ci) {
            #pragma unroll
            for (int mi = 0; mi < 4; mi++)
                #pragma unroll
                for (int nj = 0; nj < 4; nj++) {
                    const int row = wm*64 + mi*16 + tr;
                    const int col = (wn & 1)*32 + nj*8 + tc*2;
                    float* a = acc2[mi*4+nj];
                    d1s[row * D1S_STRIDE + col]           = a[0];
                    d1s[row * D1S_STRIDE + col + 1]       = a[1];
                    d1s[(row + 8) * D1S_STRIDE + col]     = a[2];
                    d1s[(row + 8) * D1S_STRIDE + col + 1] = a[3];
                }
        }
        __syncthreads();
        {
            const int half = tid & 1;
            const int rest = tid >> 1;          // 0..127
            const int g    = rest >> 6;
            const int cl   = rest & 63;
            const float bias = __ldg(&b2[ci * 64 + cl]);
            const int i0   = half * 25;
            const int icnt = half ? 24 : 25;
            float ps = 0.0f;
            for (int ii = 0; ii < icnt; ii++) {
                const int i = i0 + ii;
                float s = bias;
                #pragma unroll
                for (int t = 0; t < 9; t++)
                    s += adjw[i*9+t] * d1s[(g*64 + adji[i*9+t]) * D1S_STRIDE + cl];
                ps += fmaxf(s, 0.0f);
            }
            ps += __shfl_xor_sync(0xFFFFFFFFu, ps, 1);
            if (half == 0) pooled[g * C2 + ci * 64 + cl] = ps * (1.0f / 49.0f);
        }
        __syncthreads();
    }

    if (tid < BT * NCLS) {
        const int g = tid / NCLS, o = tid - g * NCLS;
        float s = __ldg(&bf[o]);
        const float* pp = pooled + g * C2;
        #pragma unroll 8
        for (int k = 0; k < C2; k++) s += pp[k] * __ldg(&Wf[k * NCLS + o]);
        out[(size_t)(b0 + g) * NCLS + o] = s;
    }
}

extern "C" void kernel_launch(void* const* d_in, const int* in_sizes, int n_in,
                              void* d_out, int out_size)
{
    const float* x  = (const float*)d_in[0];
    const float* W1 = (const float*)d_in[1];
    const float* b1 = (const float*)d_in[2];
    const float* W2 = (const float*)d_in[3];
    const float* b2 = (const float*)d_in[4];
    const float* Wf = (const float*)d_in[5];
    const float* bf = (const float*)d_in[6];
    float* out = (float*)d_out;

    const int B = in_sizes[0] / (NNODE * DIM);   // 4096

    prep_weights<<<(C1 * DIM + C1 * C2 + 255) / 256, 256>>>(W1, W2);

    cudaFuncSetAttribute(gnn_fused, cudaFuncAttributeMaxDynamicSharedMemorySize, SMEM_BYTES);
    gnn_fused<<<B / BT, TPB, SMEM_BYTES>>>(x, b1, b2, Wf, bf, out);
}